// round 15
// baseline (speedup 1.0000x reference)
#include <cuda_runtime.h>
#include <cuda_fp16.h>
#include <cstdint>
#include <math.h>

// ---------------- problem constants ----------------
#define BB   16
#define CC   256
#define HWSZ 1024
#define DH   32
#define HEADS 8
#define KTOP 4
#define MRC  1024
#define NWIN 64
#define EPSV 1e-5f

// pre-split weight offsets (halves)
#define WOFF_QKV 0
#define WOFF_MRG 196608
#define WOFF_W1  262144
#define WOFF_W2  524288
#define WTOT     786432

// ---------------- device scratch ----------------
__device__ float  g_qm  [BB * HEADS * NWIN * DH];
__device__ float  g_km  [BB * HEADS * NWIN * DH];
__device__ int    g_idx [BB * HEADS * NWIN * KTOP];
__device__ __half g_h0h [BB * CC  * HWSZ];
__device__ __half g_qkvh[BB * 3*CC * HWSZ];
__device__ __half g_msgh[BB * CC  * HWSZ];
__device__ __half g_x1h [BB * CC  * HWSZ];
__device__ __half g_h1h [BB * MRC * HWSZ];
__device__ __half g_h2h [BB * MRC * HWSZ];
__device__ __half g_wh  [WTOT];
__device__ __half g_wl  [196608];   // lo only for qkv (q,k rows used)

__device__ __forceinline__ float gelu_f(float x) {
    return 0.5f * x * (1.0f + erff(x * 0.7071067811865475f));
}

// ---------------- fp16 warp MMA + ldmatrix + cp.async ----------------
__device__ __forceinline__ void mma_f16(float* d, const uint32_t* a, uint32_t b0, uint32_t b1) {
    asm volatile(
        "mma.sync.aligned.m16n8k16.row.col.f32.f16.f16.f32 "
        "{%0,%1,%2,%3}, {%4,%5,%6,%7}, {%8,%9}, {%0,%1,%2,%3};"
        : "+f"(d[0]), "+f"(d[1]), "+f"(d[2]), "+f"(d[3])
        : "r"(a[0]), "r"(a[1]), "r"(a[2]), "r"(a[3]), "r"(b0), "r"(b1));
}
__device__ __forceinline__ void ldsm_x2_t(uint32_t& r0, uint32_t& r1, uint32_t addr) {
    asm volatile("ldmatrix.sync.aligned.m8n8.x2.trans.shared.b16 {%0,%1}, [%2];"
                 : "=r"(r0), "=r"(r1) : "r"(addr));
}
__device__ __forceinline__ void ldsm_x4(uint32_t* r, uint32_t addr) {
    asm volatile("ldmatrix.sync.aligned.m8n8.x4.shared.b16 {%0,%1,%2,%3}, [%4];"
                 : "=r"(r[0]), "=r"(r[1]), "=r"(r[2]), "=r"(r[3]) : "r"(addr));
}
__device__ __forceinline__ void ldsm_x4_t(uint32_t* r, uint32_t addr) {
    asm volatile("ldmatrix.sync.aligned.m8n8.x4.trans.shared.b16 {%0,%1,%2,%3}, [%4];"
                 : "=r"(r[0]), "=r"(r[1]), "=r"(r[2]), "=r"(r[3]) : "r"(addr));
}
__device__ __forceinline__ uint32_t smem_u32(const void* p) {
    uint32_t a;
    asm("{ .reg .u64 t; cvta.to.shared.u64 t, %1; cvt.u32.u64 %0, t; }" : "=r"(a) : "l"(p));
    return a;
}
__device__ __forceinline__ void cp16(uint32_t dst, const void* src) {
    asm volatile("cp.async.cg.shared.global [%0], [%1], 16;" :: "r"(dst), "l"(src) : "memory");
}
#define CP_COMMIT() asm volatile("cp.async.commit_group;" ::: "memory")
#define CP_WAIT(N)  asm volatile("cp.async.wait_group %0;" :: "n"(N) : "memory")
__device__ __forceinline__ void cvt_split(float x, __half& h, __half& l) {
    h = __float2half_rn(x);
    l = __float2half_rn(x - __half2float(h));
}

// ---------------- weight pre-split ----------------
__global__ void wsplit_k(const float* __restrict__ wqkv, const float* __restrict__ wmrg,
                         const float* __restrict__ w1,   const float* __restrict__ w2) {
    int i = blockIdx.x * 256 + threadIdx.x;
    if (i >= WTOT) return;
    if (i < WOFF_MRG) {
        __half h, l; cvt_split(wqkv[i], h, l);
        g_wh[i] = h; g_wl[i] = l;
    } else if (i < WOFF_W1) {
        g_wh[i] = __float2half_rn(wmrg[i - WOFF_MRG]);
    } else if (i < WOFF_W2) {
        g_wh[i] = __float2half_rn(w1[i - WOFF_W1]);
    } else {
        g_wh[i] = __float2half_rn(w2[i - WOFF_W2]);
    }
}

// ---------------- h0 = gelu(bn0(x)) -> fp16 ----------------
__global__ void bn0_gelu_k(const float* __restrict__ x,
                           const float* __restrict__ g, const float* __restrict__ b,
                           const float* __restrict__ m, const float* __restrict__ v) {
    int i = blockIdx.x * 256 + threadIdx.x;
    if (i >= BB * CC * HWSZ / 4) return;
    int c = (i >> 8) & (CC - 1);
    float s = g[c] * rsqrtf(v[c] + EPSV);
    float sh = b[c] - m[c] * s;
    float4 xv = ((const float4*)x)[i];
    __half2 h0 = __floats2half2_rn(gelu_f(xv.x * s + sh), gelu_f(xv.y * s + sh));
    __half2 h1 = __floats2half2_rn(gelu_f(xv.z * s + sh), gelu_f(xv.w * s + sh));
    uint2 u; u.x = *(uint32_t*)&h0; u.y = *(uint32_t*)&h1;
    ((uint2*)g_h0h)[i] = u;
}

// ---------------- tensor-core fused GEMM ----------------
// PASSES: 1 = hiW*hiA; 2 = + loW*hiA (W exact, A rounded)
// MODE 0: plain; 1: Res32 + acc + bias; 2: gelu(bn(acc)); 5: ResH + bn(acc)
// NT: CTA n-tile (128 -> 3-stage/2CTA, 64 -> 2-stage/3CTA)
template<int MODE, int PASSES, int WF32, int WF16, int KC, int NT>
__global__ void __launch_bounds__(256, (NT == 64) ? 3 : 2)
mgemm_k(const __half* __restrict__ Whg, const __half* __restrict__ Wlg,
        const __half* __restrict__ Ahg,
        float* __restrict__ Out, __half* __restrict__ Outh, int O, int Kd,
        const float* __restrict__ Res, const __half* __restrict__ ResH,
        const float* __restrict__ bias,
        const float* __restrict__ g,  const float* __restrict__ bb,
        const float* __restrict__ mm, const float* __restrict__ vv) {
    constexpr int W_STR = (KC == 64) ? 72 : 40;
    constexpr int A_STRT = NT + 8;
    constexpr int WH_B  = 128 * W_STR * 2;
    constexpr int WL_O  = WH_B;
    constexpr int AH_O  = (PASSES >= 2) ? 2 * WH_B : WH_B;
    constexpr int STG   = AH_O + KC * A_STRT * 2;
    constexpr int KSN   = KC / 16;
    constexpr int WCP   = KC / 16;
    constexpr int ACP   = KC * NT / 2048;
    constexpr int WROWDIV = KC / 8;
    constexpr int NCOL8 = NT / 8;
    constexpr int NTI   = NT / 16;        // n-tiles per warp
    constexpr int NS    = (NT == 64) ? 2 : 3;

    extern __shared__ char smc[];
    const int tid = threadIdx.x, lane = tid & 31, warp = tid >> 5;
    const int b = blockIdx.z, om = blockIdx.x * 128, n0 = blockIdx.y * NT;
    const int wm = warp >> 1, wn = warp & 1;
    const int gq = lane >> 2, tq = lane & 3;
    const uint32_t smbase = smem_u32(smc);

    const __half* Abh = Ahg + (size_t)b * Kd * HWSZ + n0;

    float acc[2][NTI][4];
    #pragma unroll
    for (int mt = 0; mt < 2; mt++)
        #pragma unroll
        for (int nt = 0; nt < NTI; nt++)
            #pragma unroll
            for (int r = 0; r < 4; r++) acc[mt][nt][r] = 0.f;

    const uint32_t aoff = (uint32_t)(((lane & 15) * A_STRT + wn * (NT / 2)) * 2);
    const uint32_t woff = (uint32_t)(((wm * 32 + (lane & 7) + ((lane >> 3) & 1) * 8) * W_STR
                                     + (lane >> 4) * 8) * 2);
    const int nch = Kd / KC;

    auto issue = [&](int ch, int st) {
        int k0 = ch * KC;
        uint32_t stu = smbase + (uint32_t)st * STG;
        #pragma unroll
        for (int it = 0; it < WCP; it++) {
            int e = tid + it * 256;
            int row = e / WROWDIV, cc = e % WROWDIV;
            cp16(stu + row * (W_STR * 2) + cc * 16,
                 Whg + (size_t)(om + row) * Kd + k0 + cc * 8);
            if (PASSES >= 2)
                cp16(stu + WL_O + row * (W_STR * 2) + cc * 16,
                     Wlg + (size_t)(om + row) * Kd + k0 + cc * 8);
        }
        #pragma unroll
        for (int it = 0; it < ACP; it++) {
            int e = tid + it * 256;
            int row = e / NCOL8, col8 = (e % NCOL8) * 8;
            cp16(stu + AH_O + (row * A_STRT + col8) * 2, Abh + (size_t)(k0 + row) * HWSZ + col8);
        }
        CP_COMMIT();
    };

    auto compute = [&](int st) {
        uint32_t stu = smbase + (uint32_t)st * STG;
        #pragma unroll
        for (int ks = 0; ks < KSN; ks++) {
            uint32_t afh[2][4], afl[2][4];
            #pragma unroll
            for (int mt = 0; mt < 2; mt++) {
                uint32_t wa = stu + woff + (uint32_t)(mt * 16 * W_STR * 2 + ks * 32);
                ldsm_x4(afh[mt], wa);
                if (PASSES >= 2) ldsm_x4(afl[mt], wa + WL_O);
            }
            uint32_t abase_h = stu + AH_O + aoff + (uint32_t)ks * (16 * A_STRT * 2);
            #pragma unroll
            for (int nt = 0; nt < NTI; nt++) {
                uint32_t bh0, bh1;
                ldsm_x2_t(bh0, bh1, abase_h + nt * 16);
                #pragma unroll
                for (int mt = 0; mt < 2; mt++) {
                    mma_f16(acc[mt][nt], afh[mt], bh0, bh1);
                    if (PASSES >= 2) mma_f16(acc[mt][nt], afl[mt], bh0, bh1);
                }
            }
        }
    };

    issue(0, 0);
    issue(1, 1);

    if (NS == 3) {
        int st = 0;
        for (int ch = 0; ch < nch; ch++) {
            if (ch + 1 < nch) { CP_WAIT(1); } else { CP_WAIT(0); }
            __syncthreads();
            if (ch + 2 < nch) {
                int st2 = st + 2; if (st2 >= 3) st2 -= 3;
                issue(ch + 2, st2);
            }
            compute(st);
            st = (st + 1 == 3) ? 0 : st + 1;
        }
    } else {
        int st = 0;
        for (int ch = 0; ch < nch; ch++) {
            if (ch + 1 < nch) { CP_WAIT(1); } else { CP_WAIT(0); }
            __syncthreads();
            compute(st);
            __syncthreads();
            if (ch + 2 < nch) issue(ch + 2, st);
            st ^= 1;
        }
    }
    __syncthreads();

    // ---- epilogue ----
    #pragma unroll
    for (int mt = 0; mt < 2; mt++) {
        int o0 = om + wm * 32 + mt * 16 + gq;
        int o1 = o0 + 8;
        float s0 = 0.f, bs0 = 0.f, s1 = 0.f, bs1 = 0.f, bi0 = 0.f, bi1 = 0.f;
        if (MODE == 2 || MODE == 5) {
            s0 = g[o0] * rsqrtf(vv[o0] + EPSV); bs0 = bb[o0] - mm[o0] * s0;
            s1 = g[o1] * rsqrtf(vv[o1] + EPSV); bs1 = bb[o1] - mm[o1] * s1;
        }
        if (MODE == 1) { bi0 = bias[o0]; bi1 = bias[o1]; }
        #pragma unroll
        for (int nt = 0; nt < NTI; nt++) {
            int n = n0 + wn * (NT / 2) + nt * 8 + 2 * tq;
            size_t oi0 = ((size_t)b * O + o0) * HWSZ + n;
            size_t oi1 = ((size_t)b * O + o1) * HWSZ + n;
            float r0 = acc[mt][nt][0], r1 = acc[mt][nt][1];
            float r2 = acc[mt][nt][2], r3 = acc[mt][nt][3];
            if (MODE == 1) {
                float2 e0 = *(const float2*)&Res[oi0];
                float2 e1 = *(const float2*)&Res[oi1];
                r0 += e0.x + bi0; r1 += e0.y + bi0;
                r2 += e1.x + bi1; r3 += e1.y + bi1;
            }
            if (MODE == 2) {
                r0 = gelu_f(r0 * s0 + bs0); r1 = gelu_f(r1 * s0 + bs0);
                r2 = gelu_f(r2 * s1 + bs1); r3 = gelu_f(r3 * s1 + bs1);
            }
            if (MODE == 5) {
                __half2 e0 = *(const __half2*)&ResH[oi0];
                __half2 e1 = *(const __half2*)&ResH[oi1];
                r0 = __low2float(e0) + r0 * s0 + bs0;
                r1 = __high2float(e0) + r1 * s0 + bs0;
                r2 = __low2float(e1) + r2 * s1 + bs1;
                r3 = __high2float(e1) + r3 * s1 + bs1;
            }
            if (WF32) {
                float2 v0 = {r0, r1}, v1 = {r2, r3};
                *(float2*)&Out[oi0] = v0;
                *(float2*)&Out[oi1] = v1;
            }
            if (WF16) {
                __half2 hv0 = __floats2half2_rn(r0, r1);
                __half2 hv1 = __floats2half2_rn(r2, r3);
                *(__half2*)&Outh[oi0] = hv0;
                *(__half2*)&Outh[oi1] = hv1;
            }
        }
    }
}

// ---------------- window means: block per (b,h,dpair) ----------------
__global__ void wmean_k() {
    int bid = blockIdx.x;
    int dp = bid & 15, h = (bid >> 4) & 7, b = bid >> 7;
    int d0 = dp * 2;
    int tid = threadIdx.x;
    __shared__ float spq[2][256], spk[2][256];
    const __half* qpl = g_qkvh + ((size_t)b * 3 * CC + h * DH + d0) * HWSZ;
    const __half* kpl = qpl + (size_t)CC * HWSZ;
    #pragma unroll
    for (int i = 0; i < 2; i++) {
        uint2 uq = ((const uint2*)(qpl + (size_t)i * HWSZ))[tid];
        uint2 uk = ((const uint2*)(kpl + (size_t)i * HWSZ))[tid];
        __half2 qa = *(__half2*)&uq.x, qb = *(__half2*)&uq.y;
        __half2 ka = *(__half2*)&uk.x, kb = *(__half2*)&uk.y;
        spq[i][tid] = __low2float(qa) + __high2float(qa) + __low2float(qb) + __high2float(qb);
        spk[i][tid] = __low2float(ka) + __high2float(ka) + __low2float(kb) + __high2float(kb);
    }
    __syncthreads();
    if (tid < 128) {
        int i = tid >> 6, w = tid & 63;
        int wy = w >> 3, wx = w & 7;
        int base = wy * 32 + wx;
        float sq = spq[i][base] + spq[i][base + 8] + spq[i][base + 16] + spq[i][base + 24];
        float sk = spk[i][base] + spk[i][base + 8] + spk[i][base + 16] + spk[i][base + 24];
        size_t o = ((size_t)(b * 8 + h) * 64 + w) * DH + d0 + i;
        g_qm[o] = sq * 0.0625f;
        g_km[o] = sk * 0.0625f;
    }
}

// ---------------- affinity + exact top-4 (2-way split) ----------------
__global__ void topk_k() {
    int bh = blockIdx.x >> 1;
    int half = blockIdx.x & 1;
    __shared__ float kt[32][65];
    __shared__ float qs[64][32];
    int tid = threadIdx.x, warp = tid >> 5, lane = tid & 31;
    for (int e = tid; e < 2048; e += 256) {
        int j = e >> 5, d = e & 31;
        kt[d][j] = g_km[(size_t)bh * 2048 + e];
        qs[j][d] = g_qm[(size_t)bh * 2048 + e];
    }
    __syncthreads();
    for (int ii = 0; ii < 4; ii++) {
        int i = half * 32 + warp * 4 + ii;
        float s0 = 0.f, s1 = 0.f;
        #pragma unroll
        for (int d = 0; d < 32; d++) {
            float q = qs[i][d];
            s0 += q * kt[d][lane];
            s1 += q * kt[d][lane + 32];
        }
        float v0 = s0, v1 = s1;
        #pragma unroll
        for (int t = 0; t < KTOP; t++) {
            float bvv; int bj;
            if (v0 >= v1) { bvv = v0; bj = lane; } else { bvv = v1; bj = lane + 32; }
            #pragma unroll
            for (int off = 16; off; off >>= 1) {
                float ov = __shfl_xor_sync(0xffffffffu, bvv, off);
                int   oj = __shfl_xor_sync(0xffffffffu, bj,  off);
                if (ov > bvv || (ov == bvv && oj < bj)) { bvv = ov; bj = oj; }
            }
            if (lane == 0) g_idx[((size_t)bh * 64 + i) * KTOP + t] = bj;
            if (bj == lane)      v0 = -INFINITY;
            if (bj == lane + 32) v1 = -INFINITY;
        }
    }
}

// ---------------- gathered window attention (HMMA, ldmatrix fragments) ----------------
#define QT_STR 24
#define KV_STR 72
#define SS_STR 68
#define P_STR  72
__global__ void __launch_bounds__(128) attn_k() {
    int bid = blockIdx.x;
    int n = bid & 63;
    int h = (bid >> 6) & 7;
    int b = bid >> 9;
    __shared__ __half qh[32 * QT_STR];
    __shared__ __half kh[32 * KV_STR];
    __shared__ __half vh[32 * KV_STR];
    __shared__ float  ss[16 * SS_STR];
    __shared__ __half ph[16 * P_STR];
    __shared__ int    widx[KTOP];
    int tid = threadIdx.x;
    if (tid < KTOP) widx[tid] = g_idx[(size_t)bid * KTOP + tid];
    __syncthreads();

    int wy = n >> 3, wx = n & 7;
    const __half* qbase = g_qkvh + ((size_t)b * 3 * CC + h * DH) * HWSZ;
    const __half* kbase = qbase + (size_t)CC * HWSZ;
    const __half* vbase = qbase + (size_t)2 * CC * HWSZ;

    {
        int d = tid >> 2, tj = tid & 3;
        int hw = ((wy * 4 + tj) << 5) + wx * 4;
        uint2 u = *(const uint2*)(qbase + (size_t)d * HWSZ + hw);
        *(uint2*)&qh[d * QT_STR + tj * 4] = u;
    }
    for (int e = tid; e < 512; e += 128) {
        int d = e >> 4, kq = e & 15;
        int j = widx[kq >> 2];
        int tj = kq & 3;
        int hw = (((j >> 3) * 4 + tj) << 5) + (j & 7) * 4;
        uint2 uk = *(const uint2*)(kbase + (size_t)d * HWSZ + hw);
        uint2 uv = *(const uint2*)(vbase + (size_t)d * HWSZ + hw);
        *(uint2*)&kh[d * KV_STR + kq * 4] = uk;
        *(uint2*)&vh[d * KV_STR + kq * 4] = uv;
    }
    __syncthreads();

    int warp = tid >> 5, lane = tid & 31;
    int gq = lane >> 2, tq = lane & 3;
    const float scale = 0.17677669529663687f;
    const uint32_t qsm = smem_u32(qh);
    const uint32_t ksm = smem_u32(kh);
    const uint32_t qloff = (uint32_t)((((lane & 7) + (lane >> 4) * 8) * QT_STR
                                      + ((lane >> 3) & 1) * 8) * 2);
    const uint32_t kloff = (uint32_t)(((lane & 15) * KV_STR + warp * 16) * 2);

    {
        float sc0[4] = {0.f, 0.f, 0.f, 0.f};
        float sc1[4] = {0.f, 0.f, 0.f, 0.f};
        #pragma unroll
        for (int ks = 0; ks < 2; ks++) {
            uint32_t ah[4];
            ldsm_x4_t(ah, qsm + qloff + (uint32_t)(ks * 16 * QT_STR * 2));
            uint32_t kb0, kb1;
            ldsm_x2_t(kb0, kb1, ksm + kloff + (uint32_t)(ks * 16 * KV_STR * 2));
            mma_f16(sc0, ah, kb0, kb1);
            uint32_t kb2, kb3;
            ldsm_x2_t(kb2, kb3, ksm + kloff + (uint32_t)(ks * 16 * KV_STR * 2) + 16);
            mma_f16(sc1, ah, kb2, kb3);
        }
        #pragma unroll
        for (int nt = 0; nt < 2; nt++) {
            const float* sc = nt ? sc1 : sc0;
            int c0 = warp * 16 + nt * 8 + 2 * tq;
            ss[gq * SS_STR + c0]           = sc[0] * scale;
            ss[gq * SS_STR + c0 + 1]       = sc[1] * scale;
            ss[(gq + 8) * SS_STR + c0]     = sc[2] * scale;
            ss[(gq + 8) * SS_STR + c0 + 1] = sc[3] * scale;
        }
    }
    __syncthreads();

    #pragma unroll
    for (int rr = 0; rr < 4; rr++) {
        int row = warp * 4 + rr;
        float s0 = ss[row * SS_STR + lane];
        float s1 = ss[row * SS_STR + lane + 32];
        float mx = fmaxf(s0, s1);
        #pragma unroll
        for (int off = 16; off; off >>= 1) mx = fmaxf(mx, __shfl_xor_sync(0xffffffffu, mx, off));
        float e0 = expf(s0 - mx), e1 = expf(s1 - mx);
        float sum = e0 + e1;
        #pragma unroll
        for (int off = 16; off; off >>= 1) sum += __shfl_xor_sync(0xffffffffu, sum, off);
        float inv = 1.0f / sum;
        ph[row * P_STR + lane]      = __float2half_rn(e0 * inv);
        ph[row * P_STR + lane + 32] = __float2half_rn(e1 * inv);
    }
    __syncthreads();

    {
        float f[4] = {0.f, 0.f, 0.f, 0.f};
        #pragma unroll
        for (int ks = 0; ks < 4; ks++) {
            int cb = ks * 16 + 2 * tq;
            uint32_t ah[4];
            ah[0] = *(const uint32_t*)&ph[gq * P_STR + cb];
            ah[1] = *(const uint32_t*)&ph[(gq + 8) * P_STR + cb];
            ah[2] = *(const uint32_t*)&ph[gq * P_STR + cb + 8];
            ah[3] = *(const uint32_t*)&ph[(gq + 8) * P_STR + cb + 8];
            int d = warp * 8 + gq;
            uint32_t bh0 = *(const uint32_t*)&vh[d * KV_STR + cb];
            uint32_t bh1 = *(const uint32_t*)&vh[d * KV_STR + cb + 8];
            mma_f16(f, ah, bh0, bh1);
        }
        __half* mbase = g_msgh + ((size_t)b * CC + h * DH) * HWSZ;
        int d0 = warp * 8 + 2 * tq;
        int hwA = ((wy * 4 + (gq >> 2)) << 5) + wx * 4 + (gq & 3);
        int hwB = ((wy * 4 + ((gq + 8) >> 2)) << 5) + wx * 4 + ((gq + 8) & 3);
        mbase[(size_t)d0 * HWSZ + hwA]       = __float2half_rn(f[0]);
        mbase[(size_t)(d0 + 1) * HWSZ + hwA] = __float2half_rn(f[1]);
        mbase[(size_t)d0 * HWSZ + hwB]       = __float2half_rn(f[2]);
        mbase[(size_t)(d0 + 1) * HWSZ + hwB] = __float2half_rn(f[3]);
    }
}

// ---------------- depthwise 3x3 + bn2 + gelu (2 channels/block) ----------------
__global__ void dw_k(const float* __restrict__ dw,
                     const float* __restrict__ g2, const float* __restrict__ b2,
                     const float* __restrict__ m2, const float* __restrict__ v2) {
    int bc0 = blockIdx.x * 2;
    __shared__ float t[2][1024];
    __shared__ float wsh[2][9];
    int tid = threadIdx.x;
    #pragma unroll
    for (int i = 0; i < 2; i++) {
        const __half* p = g_h1h + (size_t)(bc0 + i) * HWSZ;
        uint2 u = ((const uint2*)p)[tid];
        __half2 a = *(__half2*)&u.x, bp = *(__half2*)&u.y;
        float4 f;
        f.x = __low2float(a);  f.y = __high2float(a);
        f.z = __low2float(bp); f.w = __high2float(bp);
        ((float4*)t[i])[tid] = f;
    }
    if (tid < 18) {
        int i = tid / 9, w = tid % 9;
        wsh[i][w] = dw[((bc0 + i) & (MRC - 1)) * 9 + w];
    }
    __syncthreads();
    int y = tid >> 3, x0 = (tid & 7) * 4;
    #pragma unroll
    for (int i = 0; i < 2; i++) {
        int c = (bc0 + i) & (MRC - 1);
        float s = g2[c] * rsqrtf(v2[c] + EPSV);
        float bs = b2[c] - m2[c] * s;
        __half* outp = g_h2h + (size_t)(bc0 + i) * HWSZ;
        float rp[4];
        #pragma unroll
        for (int j = 0; j < 4; j++) {
            int x = x0 + j;
            float acc = 0.f;
            #pragma unroll
            for (int dy = -1; dy <= 1; dy++) {
                int yy = y + dy;
                if (yy < 0 || yy > 31) continue;
                #pragma unroll
                for (int dx = -1; dx <= 1; dx++) {
                    int xx = x + dx;
                    if (xx < 0 || xx > 31) continue;
                    acc += wsh[i][(dy + 1) * 3 + (dx + 1)] * t[i][yy * 32 + xx];
                }
            }
            rp[j] = gelu_f(acc * s + bs);
        }
        __half2 o0 = __floats2half2_rn(rp[0], rp[1]);
        __half2 o1 = __floats2half2_rn(rp[2], rp[3]);
        uint2 u; u.x = *(uint32_t*)&o0; u.y = *(uint32_t*)&o1;
        ((uint2*)outp)[tid] = u;
    }
}

// ---------------- launcher ----------------
extern "C" void kernel_launch(void* const* d_in, const int* in_sizes, int n_in,
                              void* d_out, int out_size) {
    const float* x      = (const float*)d_in[0];
    const float* bn0_g  = (const float*)d_in[1];
    const float* bn0_b  = (const float*)d_in[2];
    const float* bn0_m  = (const float*)d_in[3];
    const float* bn0_v  = (const float*)d_in[4];
    const float* w_qkv  = (const float*)d_in[5];
    const float* w_mrg  = (const float*)d_in[6];
    const float* b_mrg  = (const float*)d_in[7];
    const float* w1     = (const float*)d_in[8];
    const float* bn1_g  = (const float*)d_in[9];
    const float* bn1_b  = (const float*)d_in[10];
    const float* bn1_m  = (const float*)d_in[11];
    const float* bn1_v  = (const float*)d_in[12];
    const float* dw     = (const float*)d_in[13];
    const float* bn2_g  = (const float*)d_in[14];
    const float* bn2_b  = (const float*)d_in[15];
    const float* bn2_m  = (const float*)d_in[16];
    const float* bn2_v  = (const float*)d_in[17];
    const float* w2     = (const float*)d_in[18];
    const float* bn3_g  = (const float*)d_in[19];
    const float* bn3_b  = (const float*)d_in[20];
    const float* bn3_m  = (const float*)d_in[21];
    const float* bn3_v  = (const float*)d_in[22];

    __half *wh, *wl, *h0h, *qkvh, *msgh, *x1h, *h1h, *h2h;
    cudaGetSymbolAddress((void**)&wh,   g_wh);
    cudaGetSymbolAddress((void**)&wl,   g_wl);
    cudaGetSymbolAddress((void**)&h0h,  g_h0h);
    cudaGetSymbolAddress((void**)&qkvh, g_qkvh);
    cudaGetSymbolAddress((void**)&msgh, g_msgh);
    cudaGetSymbolAddress((void**)&x1h,  g_x1h);
    cudaGetSymbolAddress((void**)&h1h,  g_h1h);
    cudaGetSymbolAddress((void**)&h2h,  g_h2h);

    // smem: qk (KC=32, 2-pass, NT=128): 3*29184=87552
    //       1-pass KC=64 NT=64: 2*(18432+9216)=55296
    cudaFuncSetAttribute((const void*)mgemm_k<0,2,0,1,32,128>, cudaFuncAttributeMaxDynamicSharedMemorySize, 87552);
    cudaFuncSetAttribute((const void*)mgemm_k<0,1,0,1,64,64>,  cudaFuncAttributeMaxDynamicSharedMemorySize, 55296);
    cudaFuncSetAttribute((const void*)mgemm_k<1,1,0,1,64,64>,  cudaFuncAttributeMaxDynamicSharedMemorySize, 55296);
    cudaFuncSetAttribute((const void*)mgemm_k<2,1,0,1,64,64>,  cudaFuncAttributeMaxDynamicSharedMemorySize, 55296);
    cudaFuncSetAttribute((const void*)mgemm_k<5,1,1,0,64,64>,  cudaFuncAttributeMaxDynamicSharedMemorySize, 55296);

    // 0. pre-split weights to fp16
    wsplit_k<<<(WTOT + 255) / 256, 256>>>(w_qkv, w_mrg, w1, w2);

    // 1. h0 = gelu(bn0(x)) -> fp16
    bn0_gelu_k<<<(BB * CC * HWSZ / 4 + 255) / 256, 256>>>(x, bn0_g, bn0_b, bn0_m, bn0_v);

    // 2a. q,k = w_qkv[0:512] @ h0   (2-pass, KC=32, NT=128)
    mgemm_k<0,2,0,1,32,128><<<dim3(4, 8, BB), 256, 87552>>>(
        wh + WOFF_QKV, wl, h0h, nullptr, qkvh, 768, 256,
        nullptr, nullptr, nullptr, nullptr, nullptr, nullptr, nullptr);

    // 2b. v = w_qkv[512:768] @ h0   (1-pass, KC=64, NT=64)
    mgemm_k<0,1,0,1,64,64><<<dim3(2, 16, BB), 256, 55296>>>(
        wh + WOFF_QKV + 512 * 256, nullptr, h0h, nullptr,
        qkvh + (size_t)512 * HWSZ, 768, 256,
        nullptr, nullptr, nullptr, nullptr, nullptr, nullptr, nullptr);

    // 3. window means (2 d per block)
    wmean_k<<<BB * HEADS * DH / 2, 256>>>();

    // 4. affinity + top-4 (2-way split)
    topk_k<<<BB * HEADS * 2, 256>>>();

    // 5. gathered attention
    attn_k<<<BB * HEADS * NWIN, 128>>>();

    // 6. x1h = fp16(x + w_merge @ msg + b_merge)   (KC=64, NT=64)
    mgemm_k<1,1,0,1,64,64><<<dim3(CC / 128, 16, BB), 256, 55296>>>(
        wh + WOFF_MRG, nullptr, msgh, nullptr, x1h, CC, 256,
        x, nullptr, b_mrg, nullptr, nullptr, nullptr, nullptr);

    // 7. h1 = gelu(bn1(w1 @ x1h)) -> fp16   (KC=64, NT=64)
    mgemm_k<2,1,0,1,64,64><<<dim3(MRC / 128, 16, BB), 256, 55296>>>(
        wh + WOFF_W1, nullptr, x1h, nullptr, h1h, MRC, 256,
        nullptr, nullptr, nullptr, bn1_g, bn1_b, bn1_m, bn1_v);

    // 8. h2 = gelu(bn2(dwconv3x3(h1))) -> fp16   (2 channels/block)
    dw_k<<<BB * MRC / 2, 256>>>(dw, bn2_g, bn2_b, bn2_m, bn2_v);

    // 9. out = x1h + bn3(w2 @ h2)   (KC=64, NT=64)
    mgemm_k<5,1,1,0,64,64><<<dim3(CC / 128, 16, BB), 256, 55296>>>(
        wh + WOFF_W2, nullptr, h2h, (float*)d_out, nullptr, CC, 1024,
        nullptr, x1h, nullptr, bn3_g, bn3_b, bn3_m, bn3_v);
}

// round 16
// speedup vs baseline: 1.0246x; 1.0246x over previous
#include <cuda_runtime.h>
#include <cuda_fp16.h>
#include <cstdint>
#include <math.h>

// ---------------- problem constants ----------------
#define BB   16
#define CC   256
#define HWSZ 1024
#define DH   32
#define HEADS 8
#define KTOP 4
#define MRC  1024
#define NWIN 64
#define EPSV 1e-5f

// pre-split weight offsets (halves)
#define WOFF_QKV 0
#define WOFF_MRG 196608
#define WOFF_W1  262144
#define WOFF_W2  524288
#define WTOT     786432

// ---------------- device scratch ----------------
__device__ float  g_qm  [BB * HEADS * NWIN * DH];
__device__ float  g_km  [BB * HEADS * NWIN * DH];
__device__ int    g_idx [BB * HEADS * NWIN * KTOP];
__device__ __half g_h0h [BB * CC  * HWSZ];
__device__ __half g_qkvh[BB * 3*CC * HWSZ];
__device__ __half g_msgh[BB * CC  * HWSZ];
__device__ __half g_x1h [BB * CC  * HWSZ];
__device__ __half g_h1h [BB * MRC * HWSZ];
__device__ __half g_h2h [BB * MRC * HWSZ];
__device__ __half g_wh  [WTOT];
__device__ __half g_wl  [196608];   // lo only for qkv (q,k rows used)

__device__ __forceinline__ float gelu_f(float x) {
    return 0.5f * x * (1.0f + erff(x * 0.7071067811865475f));
}

// ---------------- fp16 warp MMA + ldmatrix + cp.async ----------------
__device__ __forceinline__ void mma_f16(float* d, const uint32_t* a, uint32_t b0, uint32_t b1) {
    asm volatile(
        "mma.sync.aligned.m16n8k16.row.col.f32.f16.f16.f32 "
        "{%0,%1,%2,%3}, {%4,%5,%6,%7}, {%8,%9}, {%0,%1,%2,%3};"
        : "+f"(d[0]), "+f"(d[1]), "+f"(d[2]), "+f"(d[3])
        : "r"(a[0]), "r"(a[1]), "r"(a[2]), "r"(a[3]), "r"(b0), "r"(b1));
}
__device__ __forceinline__ void ldsm_x2_t(uint32_t& r0, uint32_t& r1, uint32_t addr) {
    asm volatile("ldmatrix.sync.aligned.m8n8.x2.trans.shared.b16 {%0,%1}, [%2];"
                 : "=r"(r0), "=r"(r1) : "r"(addr));
}
__device__ __forceinline__ void ldsm_x4(uint32_t* r, uint32_t addr) {
    asm volatile("ldmatrix.sync.aligned.m8n8.x4.shared.b16 {%0,%1,%2,%3}, [%4];"
                 : "=r"(r[0]), "=r"(r[1]), "=r"(r[2]), "=r"(r[3]) : "r"(addr));
}
__device__ __forceinline__ void ldsm_x4_t(uint32_t* r, uint32_t addr) {
    asm volatile("ldmatrix.sync.aligned.m8n8.x4.trans.shared.b16 {%0,%1,%2,%3}, [%4];"
                 : "=r"(r[0]), "=r"(r[1]), "=r"(r[2]), "=r"(r[3]) : "r"(addr));
}
__device__ __forceinline__ uint32_t smem_u32(const void* p) {
    uint32_t a;
    asm("{ .reg .u64 t; cvta.to.shared.u64 t, %1; cvt.u32.u64 %0, t; }" : "=r"(a) : "l"(p));
    return a;
}
__device__ __forceinline__ void cp16(uint32_t dst, const void* src) {
    asm volatile("cp.async.cg.shared.global [%0], [%1], 16;" :: "r"(dst), "l"(src) : "memory");
}
#define CP_COMMIT() asm volatile("cp.async.commit_group;" ::: "memory")
#define CP_WAIT(N)  asm volatile("cp.async.wait_group %0;" :: "n"(N) : "memory")
__device__ __forceinline__ void cvt_split(float x, __half& h, __half& l) {
    h = __float2half_rn(x);
    l = __float2half_rn(x - __half2float(h));
}

#define A_STR 136

// ---------------- weight pre-split ----------------
__global__ void wsplit_k(const float* __restrict__ wqkv, const float* __restrict__ wmrg,
                         const float* __restrict__ w1,   const float* __restrict__ w2) {
    int i = blockIdx.x * 256 + threadIdx.x;
    if (i >= WTOT) return;
    if (i < WOFF_MRG) {
        __half h, l; cvt_split(wqkv[i], h, l);
        g_wh[i] = h; g_wl[i] = l;
    } else if (i < WOFF_W1) {
        g_wh[i] = __float2half_rn(wmrg[i - WOFF_MRG]);
    } else if (i < WOFF_W2) {
        g_wh[i] = __float2half_rn(w1[i - WOFF_W1]);
    } else {
        g_wh[i] = __float2half_rn(w2[i - WOFF_W2]);
    }
}

// ---------------- h0 = gelu(bn0(x)) -> fp16 ----------------
__global__ void bn0_gelu_k(const float* __restrict__ x,
                           const float* __restrict__ g, const float* __restrict__ b,
                           const float* __restrict__ m, const float* __restrict__ v) {
    int i = blockIdx.x * 256 + threadIdx.x;
    if (i >= BB * CC * HWSZ / 4) return;
    int c = (i >> 8) & (CC - 1);
    float s = g[c] * rsqrtf(v[c] + EPSV);
    float sh = b[c] - m[c] * s;
    float4 xv = ((const float4*)x)[i];
    __half2 h0 = __floats2half2_rn(gelu_f(xv.x * s + sh), gelu_f(xv.y * s + sh));
    __half2 h1 = __floats2half2_rn(gelu_f(xv.z * s + sh), gelu_f(xv.w * s + sh));
    uint2 u; u.x = *(uint32_t*)&h0; u.y = *(uint32_t*)&h1;
    ((uint2*)g_h0h)[i] = u;
}

// ---------------- tensor-core fused GEMM (cp.async 3-stage, ldmatrix, KC-chunk) ----------------
// PASSES: 1 = hiW*hiA; 2 = + loW*hiA (W exact, A rounded), lo applied only when om < lo_rows
// MODE 0: plain; 1: Res32 + acc + bias; 2: gelu(bn(acc)); 5: ResH + bn(acc)
template<int MODE, int PASSES, int WF32, int WF16, int KC>
__global__ void __launch_bounds__(256, 2)
mgemm_k(const __half* __restrict__ Whg, const __half* __restrict__ Wlg,
        const __half* __restrict__ Ahg,
        float* __restrict__ Out, __half* __restrict__ Outh, int O, int Kd, int lo_rows,
        const float* __restrict__ Res, const __half* __restrict__ ResH,
        const float* __restrict__ bias,
        const float* __restrict__ g,  const float* __restrict__ bb,
        const float* __restrict__ mm, const float* __restrict__ vv) {
    constexpr int W_STR = (KC == 64) ? 72 : 40;
    constexpr int WH_B  = 128 * W_STR * 2;
    constexpr int WL_O  = WH_B;
    constexpr int AH_O  = (PASSES >= 2) ? 2 * WH_B : WH_B;
    constexpr int STG   = AH_O + KC * A_STR * 2;
    constexpr int KSN   = KC / 16;
    constexpr int WCP   = KC / 16;
    constexpr int ACP   = KC / 16;
    constexpr int WROWDIV = KC / 8;

    extern __shared__ char smc[];
    const int tid = threadIdx.x, lane = tid & 31, warp = tid >> 5;
    const int b = blockIdx.z, om = blockIdx.x * 128, n0 = blockIdx.y * 128;
    const bool LO = (PASSES >= 2) && (om < lo_rows);
    const int wm = warp >> 1, wn = warp & 1;
    const int gq = lane >> 2, tq = lane & 3;
    const uint32_t smbase = smem_u32(smc);

    const __half* Abh = Ahg + (size_t)b * Kd * HWSZ + n0;

    float acc[2][8][4];
    #pragma unroll
    for (int mt = 0; mt < 2; mt++)
        #pragma unroll
        for (int nt = 0; nt < 8; nt++)
            #pragma unroll
            for (int r = 0; r < 4; r++) acc[mt][nt][r] = 0.f;

    const uint32_t aoff = (uint32_t)(((lane & 15) * A_STR + wn * 64) * 2);
    const uint32_t woff = (uint32_t)(((wm * 32 + (lane & 7) + ((lane >> 3) & 1) * 8) * W_STR
                                     + (lane >> 4) * 8) * 2);
    const int nch = Kd / KC;

    auto issue = [&](int ch, int st) {
        int k0 = ch * KC;
        uint32_t stu = smbase + (uint32_t)st * STG;
        #pragma unroll
        for (int it = 0; it < WCP; it++) {
            int e = tid + it * 256;
            int row = e / WROWDIV, cc = e % WROWDIV;
            cp16(stu + row * (W_STR * 2) + cc * 16,
                 Whg + (size_t)(om + row) * Kd + k0 + cc * 8);
            if (LO)
                cp16(stu + WL_O + row * (W_STR * 2) + cc * 16,
                     Wlg + (size_t)(om + row) * Kd + k0 + cc * 8);
        }
        #pragma unroll
        for (int it = 0; it < ACP; it++) {
            int e = tid + it * 256;
            int row = e >> 4, col8 = (e & 15) * 8;
            cp16(stu + AH_O + (row * A_STR + col8) * 2, Abh + (size_t)(k0 + row) * HWSZ + col8);
        }
        CP_COMMIT();
    };

    issue(0, 0);
    issue(1, 1);

    int st = 0;
    for (int ch = 0; ch < nch; ch++) {
        if (ch + 1 < nch) { CP_WAIT(1); } else { CP_WAIT(0); }
        __syncthreads();
        if (ch + 2 < nch) {
            int st2 = st + 2; if (st2 >= 3) st2 -= 3;
            issue(ch + 2, st2);
        }

        uint32_t stu = smbase + (uint32_t)st * STG;

        #pragma unroll
        for (int ks = 0; ks < KSN; ks++) {
            uint32_t afh[2][4], afl[2][4];
            #pragma unroll
            for (int mt = 0; mt < 2; mt++) {
                uint32_t wa = stu + woff + (uint32_t)(mt * 16 * W_STR * 2 + ks * 32);
                ldsm_x4(afh[mt], wa);
                if (LO) ldsm_x4(afl[mt], wa + WL_O);
            }
            uint32_t abase_h = stu + AH_O + aoff + (uint32_t)ks * (16 * A_STR * 2);
            #pragma unroll
            for (int nt = 0; nt < 8; nt++) {
                uint32_t bh0, bh1;
                ldsm_x2_t(bh0, bh1, abase_h + nt * 16);
                #pragma unroll
                for (int mt = 0; mt < 2; mt++) {
                    mma_f16(acc[mt][nt], afh[mt], bh0, bh1);
                    if (LO) mma_f16(acc[mt][nt], afl[mt], bh0, bh1);
                }
            }
        }
        st = (st + 1 == 3) ? 0 : st + 1;
    }
    __syncthreads();

    // ---- epilogue ----
    #pragma unroll
    for (int mt = 0; mt < 2; mt++) {
        int o0 = om + wm * 32 + mt * 16 + gq;
        int o1 = o0 + 8;
        float s0 = 0.f, bs0 = 0.f, s1 = 0.f, bs1 = 0.f, bi0 = 0.f, bi1 = 0.f;
        if (MODE == 2 || MODE == 5) {
            s0 = g[o0] * rsqrtf(vv[o0] + EPSV); bs0 = bb[o0] - mm[o0] * s0;
            s1 = g[o1] * rsqrtf(vv[o1] + EPSV); bs1 = bb[o1] - mm[o1] * s1;
        }
        if (MODE == 1) { bi0 = bias[o0]; bi1 = bias[o1]; }
        #pragma unroll
        for (int nt = 0; nt < 8; nt++) {
            int n = n0 + wn * 64 + nt * 8 + 2 * tq;
            size_t oi0 = ((size_t)b * O + o0) * HWSZ + n;
            size_t oi1 = ((size_t)b * O + o1) * HWSZ + n;
            float r0 = acc[mt][nt][0], r1 = acc[mt][nt][1];
            float r2 = acc[mt][nt][2], r3 = acc[mt][nt][3];
            if (MODE == 1) {
                float2 e0 = *(const float2*)&Res[oi0];
                float2 e1 = *(const float2*)&Res[oi1];
                r0 += e0.x + bi0; r1 += e0.y + bi0;
                r2 += e1.x + bi1; r3 += e1.y + bi1;
            }
            if (MODE == 2) {
                r0 = gelu_f(r0 * s0 + bs0); r1 = gelu_f(r1 * s0 + bs0);
                r2 = gelu_f(r2 * s1 + bs1); r3 = gelu_f(r3 * s1 + bs1);
            }
            if (MODE == 5) {
                __half2 e0 = *(const __half2*)&ResH[oi0];
                __half2 e1 = *(const __half2*)&ResH[oi1];
                r0 = __low2float(e0) + r0 * s0 + bs0;
                r1 = __high2float(e0) + r1 * s0 + bs0;
                r2 = __low2float(e1) + r2 * s1 + bs1;
                r3 = __high2float(e1) + r3 * s1 + bs1;
            }
            if (WF32) {
                float2 v0 = {r0, r1}, v1 = {r2, r3};
                *(float2*)&Out[oi0] = v0;
                *(float2*)&Out[oi1] = v1;
            }
            if (WF16) {
                __half2 hv0 = __floats2half2_rn(r0, r1);
                __half2 hv1 = __floats2half2_rn(r2, r3);
                *(__half2*)&Outh[oi0] = hv0;
                *(__half2*)&Outh[oi1] = hv1;
            }
        }
    }
}

// ---------------- window means: block per (b,h,dpair) ----------------
__global__ void wmean_k() {
    int bid = blockIdx.x;
    int dp = bid & 15, h = (bid >> 4) & 7, b = bid >> 7;
    int d0 = dp * 2;
    int tid = threadIdx.x;
    __shared__ float spq[2][256], spk[2][256];
    const __half* qpl = g_qkvh + ((size_t)b * 3 * CC + h * DH + d0) * HWSZ;
    const __half* kpl = qpl + (size_t)CC * HWSZ;
    #pragma unroll
    for (int i = 0; i < 2; i++) {
        uint2 uq = ((const uint2*)(qpl + (size_t)i * HWSZ))[tid];
        uint2 uk = ((const uint2*)(kpl + (size_t)i * HWSZ))[tid];
        __half2 qa = *(__half2*)&uq.x, qb = *(__half2*)&uq.y;
        __half2 ka = *(__half2*)&uk.x, kb = *(__half2*)&uk.y;
        spq[i][tid] = __low2float(qa) + __high2float(qa) + __low2float(qb) + __high2float(qb);
        spk[i][tid] = __low2float(ka) + __high2float(ka) + __low2float(kb) + __high2float(kb);
    }
    __syncthreads();
    if (tid < 128) {
        int i = tid >> 6, w = tid & 63;
        int wy = w >> 3, wx = w & 7;
        int base = wy * 32 + wx;
        float sq = spq[i][base] + spq[i][base + 8] + spq[i][base + 16] + spq[i][base + 24];
        float sk = spk[i][base] + spk[i][base + 8] + spk[i][base + 16] + spk[i][base + 24];
        size_t o = ((size_t)(b * 8 + h) * 64 + w) * DH + d0 + i;
        g_qm[o] = sq * 0.0625f;
        g_km[o] = sk * 0.0625f;
    }
}

// ---------------- affinity + exact top-4 (2-way split) ----------------
__global__ void topk_k() {
    int bh = blockIdx.x >> 1;
    int half = blockIdx.x & 1;
    __shared__ float kt[32][65];
    __shared__ float qs[64][32];
    int tid = threadIdx.x, warp = tid >> 5, lane = tid & 31;
    for (int e = tid; e < 2048; e += 256) {
        int j = e >> 5, d = e & 31;
        kt[d][j] = g_km[(size_t)bh * 2048 + e];
        qs[j][d] = g_qm[(size_t)bh * 2048 + e];
    }
    __syncthreads();
    for (int ii = 0; ii < 4; ii++) {
        int i = half * 32 + warp * 4 + ii;
        float s0 = 0.f, s1 = 0.f;
        #pragma unroll
        for (int d = 0; d < 32; d++) {
            float q = qs[i][d];
            s0 += q * kt[d][lane];
            s1 += q * kt[d][lane + 32];
        }
        float v0 = s0, v1 = s1;
        #pragma unroll
        for (int t = 0; t < KTOP; t++) {
            float bvv; int bj;
            if (v0 >= v1) { bvv = v0; bj = lane; } else { bvv = v1; bj = lane + 32; }
            #pragma unroll
            for (int off = 16; off; off >>= 1) {
                float ov = __shfl_xor_sync(0xffffffffu, bvv, off);
                int   oj = __shfl_xor_sync(0xffffffffu, bj,  off);
                if (ov > bvv || (ov == bvv && oj < bj)) { bvv = ov; bj = oj; }
            }
            if (lane == 0) g_idx[((size_t)bh * 64 + i) * KTOP + t] = bj;
            if (bj == lane)      v0 = -INFINITY;
            if (bj == lane + 32) v1 = -INFINITY;
        }
    }
}

// ---------------- gathered window attention (HMMA, ldmatrix fragments) ----------------
#define QT_STR 24
#define KV_STR 72
#define SS_STR 68
#define P_STR  72
__global__ void __launch_bounds__(128) attn_k() {
    int bid = blockIdx.x;
    int n = bid & 63;
    int h = (bid >> 6) & 7;
    int b = bid >> 9;
    __shared__ __half qh[32 * QT_STR];
    __shared__ __half kh[32 * KV_STR];
    __shared__ __half vh[32 * KV_STR];
    __shared__ float  ss[16 * SS_STR];
    __shared__ __half ph[16 * P_STR];
    __shared__ int    widx[KTOP];
    int tid = threadIdx.x;
    if (tid < KTOP) widx[tid] = g_idx[(size_t)bid * KTOP + tid];
    __syncthreads();

    int wy = n >> 3, wx = n & 7;
    const __half* qbase = g_qkvh + ((size_t)b * 3 * CC + h * DH) * HWSZ;
    const __half* kbase = qbase + (size_t)CC * HWSZ;
    const __half* vbase = qbase + (size_t)2 * CC * HWSZ;

    {
        int d = tid >> 2, tj = tid & 3;
        int hw = ((wy * 4 + tj) << 5) + wx * 4;
        uint2 u = *(const uint2*)(qbase + (size_t)d * HWSZ + hw);
        *(uint2*)&qh[d * QT_STR + tj * 4] = u;
    }
    for (int e = tid; e < 512; e += 128) {
        int d = e >> 4, kq = e & 15;
        int j = widx[kq >> 2];
        int tj = kq & 3;
        int hw = (((j >> 3) * 4 + tj) << 5) + (j & 7) * 4;
        uint2 uk = *(const uint2*)(kbase + (size_t)d * HWSZ + hw);
        uint2 uv = *(const uint2*)(vbase + (size_t)d * HWSZ + hw);
        *(uint2*)&kh[d * KV_STR + kq * 4] = uk;
        *(uint2*)&vh[d * KV_STR + kq * 4] = uv;
    }
    __syncthreads();

    int warp = tid >> 5, lane = tid & 31;
    int gq = lane >> 2, tq = lane & 3;
    const float scale = 0.17677669529663687f;
    const uint32_t qsm = smem_u32(qh);
    const uint32_t ksm = smem_u32(kh);
    const uint32_t qloff = (uint32_t)((((lane & 7) + (lane >> 4) * 8) * QT_STR
                                      + ((lane >> 3) & 1) * 8) * 2);
    const uint32_t kloff = (uint32_t)(((lane & 15) * KV_STR + warp * 16) * 2);

    {
        float sc0[4] = {0.f, 0.f, 0.f, 0.f};
        float sc1[4] = {0.f, 0.f, 0.f, 0.f};
        #pragma unroll
        for (int ks = 0; ks < 2; ks++) {
            uint32_t ah[4];
            ldsm_x4_t(ah, qsm + qloff + (uint32_t)(ks * 16 * QT_STR * 2));
            uint32_t kb0, kb1;
            ldsm_x2_t(kb0, kb1, ksm + kloff + (uint32_t)(ks * 16 * KV_STR * 2));
            mma_f16(sc0, ah, kb0, kb1);
            uint32_t kb2, kb3;
            ldsm_x2_t(kb2, kb3, ksm + kloff + (uint32_t)(ks * 16 * KV_STR * 2) + 16);
            mma_f16(sc1, ah, kb2, kb3);
        }
        #pragma unroll
        for (int nt = 0; nt < 2; nt++) {
            const float* sc = nt ? sc1 : sc0;
            int c0 = warp * 16 + nt * 8 + 2 * tq;
            ss[gq * SS_STR + c0]           = sc[0] * scale;
            ss[gq * SS_STR + c0 + 1]       = sc[1] * scale;
            ss[(gq + 8) * SS_STR + c0]     = sc[2] * scale;
            ss[(gq + 8) * SS_STR + c0 + 1] = sc[3] * scale;
        }
    }
    __syncthreads();

    #pragma unroll
    for (int rr = 0; rr < 4; rr++) {
        int row = warp * 4 + rr;
        float s0 = ss[row * SS_STR + lane];
        float s1 = ss[row * SS_STR + lane + 32];
        float mx = fmaxf(s0, s1);
        #pragma unroll
        for (int off = 16; off; off >>= 1) mx = fmaxf(mx, __shfl_xor_sync(0xffffffffu, mx, off));
        float e0 = expf(s0 - mx), e1 = expf(s1 - mx);
        float sum = e0 + e1;
        #pragma unroll
        for (int off = 16; off; off >>= 1) sum += __shfl_xor_sync(0xffffffffu, sum, off);
        float inv = 1.0f / sum;
        ph[row * P_STR + lane]      = __float2half_rn(e0 * inv);
        ph[row * P_STR + lane + 32] = __float2half_rn(e1 * inv);
    }
    __syncthreads();

    {
        float f[4] = {0.f, 0.f, 0.f, 0.f};
        #pragma unroll
        for (int ks = 0; ks < 4; ks++) {
            int cb = ks * 16 + 2 * tq;
            uint32_t ah[4];
            ah[0] = *(const uint32_t*)&ph[gq * P_STR + cb];
            ah[1] = *(const uint32_t*)&ph[(gq + 8) * P_STR + cb];
            ah[2] = *(const uint32_t*)&ph[gq * P_STR + cb + 8];
            ah[3] = *(const uint32_t*)&ph[(gq + 8) * P_STR + cb + 8];
            int d = warp * 8 + gq;
            uint32_t bh0 = *(const uint32_t*)&vh[d * KV_STR + cb];
            uint32_t bh1 = *(const uint32_t*)&vh[d * KV_STR + cb + 8];
            mma_f16(f, ah, bh0, bh1);
        }
        __half* mbase = g_msgh + ((size_t)b * CC + h * DH) * HWSZ;
        int d0 = warp * 8 + 2 * tq;
        int hwA = ((wy * 4 + (gq >> 2)) << 5) + wx * 4 + (gq & 3);
        int hwB = ((wy * 4 + ((gq + 8) >> 2)) << 5) + wx * 4 + ((gq + 8) & 3);
        mbase[(size_t)d0 * HWSZ + hwA]       = __float2half_rn(f[0]);
        mbase[(size_t)(d0 + 1) * HWSZ + hwA] = __float2half_rn(f[1]);
        mbase[(size_t)d0 * HWSZ + hwB]       = __float2half_rn(f[2]);
        mbase[(size_t)(d0 + 1) * HWSZ + hwB] = __float2half_rn(f[3]);
    }
}

// ---------------- depthwise 3x3 + bn2 + gelu (2 channels/block) ----------------
__global__ void dw_k(const float* __restrict__ dw,
                     const float* __restrict__ g2, const float* __restrict__ b2,
                     const float* __restrict__ m2, const float* __restrict__ v2) {
    int bc0 = blockIdx.x * 2;
    __shared__ float t[2][1024];
    __shared__ float wsh[2][9];
    int tid = threadIdx.x;
    #pragma unroll
    for (int i = 0; i < 2; i++) {
        const __half* p = g_h1h + (size_t)(bc0 + i) * HWSZ;
        uint2 u = ((const uint2*)p)[tid];
        __half2 a = *(__half2*)&u.x, bp = *(__half2*)&u.y;
        float4 f;
        f.x = __low2float(a);  f.y = __high2float(a);
        f.z = __low2float(bp); f.w = __high2float(bp);
        ((float4*)t[i])[tid] = f;
    }
    if (tid < 18) {
        int i = tid / 9, w = tid % 9;
        wsh[i][w] = dw[((bc0 + i) & (MRC - 1)) * 9 + w];
    }
    __syncthreads();
    int y = tid >> 3, x0 = (tid & 7) * 4;
    #pragma unroll
    for (int i = 0; i < 2; i++) {
        int c = (bc0 + i) & (MRC - 1);
        float s = g2[c] * rsqrtf(v2[c] + EPSV);
        float bs = b2[c] - m2[c] * s;
        __half* outp = g_h2h + (size_t)(bc0 + i) * HWSZ;
        float rp[4];
        #pragma unroll
        for (int j = 0; j < 4; j++) {
            int x = x0 + j;
            float acc = 0.f;
            #pragma unroll
            for (int dy = -1; dy <= 1; dy++) {
                int yy = y + dy;
                if (yy < 0 || yy > 31) continue;
                #pragma unroll
                for (int dx = -1; dx <= 1; dx++) {
                    int xx = x + dx;
                    if (xx < 0 || xx > 31) continue;
                    acc += wsh[i][(dy + 1) * 3 + (dx + 1)] * t[i][yy * 32 + xx];
                }
            }
            rp[j] = gelu_f(acc * s + bs);
        }
        __half2 o0 = __floats2half2_rn(rp[0], rp[1]);
        __half2 o1 = __floats2half2_rn(rp[2], rp[3]);
        uint2 u; u.x = *(uint32_t*)&o0; u.y = *(uint32_t*)&o1;
        ((uint2*)outp)[tid] = u;
    }
}

// ---------------- launcher ----------------
extern "C" void kernel_launch(void* const* d_in, const int* in_sizes, int n_in,
                              void* d_out, int out_size) {
    const float* x      = (const float*)d_in[0];
    const float* bn0_g  = (const float*)d_in[1];
    const float* bn0_b  = (const float*)d_in[2];
    const float* bn0_m  = (const float*)d_in[3];
    const float* bn0_v  = (const float*)d_in[4];
    const float* w_qkv  = (const float*)d_in[5];
    const float* w_mrg  = (const float*)d_in[6];
    const float* b_mrg  = (const float*)d_in[7];
    const float* w1     = (const float*)d_in[8];
    const float* bn1_g  = (const float*)d_in[9];
    const float* bn1_b  = (const float*)d_in[10];
    const float* bn1_m  = (const float*)d_in[11];
    const float* bn1_v  = (const float*)d_in[12];
    const float* dw     = (const float*)d_in[13];
    const float* bn2_g  = (const float*)d_in[14];
    const float* bn2_b  = (const float*)d_in[15];
    const float* bn2_m  = (const float*)d_in[16];
    const float* bn2_v  = (const float*)d_in[17];
    const float* w2     = (const float*)d_in[18];
    const float* bn3_g  = (const float*)d_in[19];
    const float* bn3_b  = (const float*)d_in[20];
    const float* bn3_m  = (const float*)d_in[21];
    const float* bn3_v  = (const float*)d_in[22];

    __half *wh, *wl, *h0h, *qkvh, *msgh, *x1h, *h1h, *h2h;
    cudaGetSymbolAddress((void**)&wh,   g_wh);
    cudaGetSymbolAddress((void**)&wl,   g_wl);
    cudaGetSymbolAddress((void**)&h0h,  g_h0h);
    cudaGetSymbolAddress((void**)&qkvh, g_qkvh);
    cudaGetSymbolAddress((void**)&msgh, g_msgh);
    cudaGetSymbolAddress((void**)&x1h,  g_x1h);
    cudaGetSymbolAddress((void**)&h1h,  g_h1h);
    cudaGetSymbolAddress((void**)&h2h,  g_h2h);

    cudaFuncSetAttribute((const void*)mgemm_k<0,2,0,1,32>, cudaFuncAttributeMaxDynamicSharedMemorySize, 87552);
    cudaFuncSetAttribute((const void*)mgemm_k<1,1,0,1,64>, cudaFuncAttributeMaxDynamicSharedMemorySize, 107520);
    cudaFuncSetAttribute((const void*)mgemm_k<2,1,0,1,64>, cudaFuncAttributeMaxDynamicSharedMemorySize, 107520);
    cudaFuncSetAttribute((const void*)mgemm_k<5,1,1,0,64>, cudaFuncAttributeMaxDynamicSharedMemorySize, 107520);

    // 0. pre-split weights to fp16
    wsplit_k<<<(WTOT + 255) / 256, 256>>>(w_qkv, w_mrg, w1, w2);

    // 1. h0 = gelu(bn0(x)) -> fp16
    bn0_gelu_k<<<(BB * CC * HWSZ / 4 + 255) / 256, 256>>>(x, bn0_g, bn0_b, bn0_m, bn0_v);

    // 2. qkv = w_qkv @ h0  (fused: rows 0-511 2-pass, rows 512-767 1-pass via lo_rows)
    mgemm_k<0,2,0,1,32><<<dim3(6, 8, BB), 256, 87552>>>(
        wh + WOFF_QKV, wl, h0h, nullptr, qkvh, 768, 256, 512,
        nullptr, nullptr, nullptr, nullptr, nullptr, nullptr, nullptr);

    // 3. window means (2 d per block)
    wmean_k<<<BB * HEADS * DH / 2, 256>>>();

    // 4. affinity + top-4 (2-way split)
    topk_k<<<BB * HEADS * 2, 256>>>();

    // 5. gathered attention
    attn_k<<<BB * HEADS * NWIN, 128>>>();

    // 6. x1h = fp16(x + w_merge @ msg + b_merge)   (KC=64)
    mgemm_k<1,1,0,1,64><<<dim3(CC / 128, 8, BB), 256, 107520>>>(
        wh + WOFF_MRG, nullptr, msgh, nullptr, x1h, CC, 256, 0,
        x, nullptr, b_mrg, nullptr, nullptr, nullptr, nullptr);

    // 7. h1 = gelu(bn1(w1 @ x1h)) -> fp16   (KC=64)
    mgemm_k<2,1,0,1,64><<<dim3(MRC / 128, 8, BB), 256, 107520>>>(
        wh + WOFF_W1, nullptr, x1h, nullptr, h1h, MRC, 256, 0,
        nullptr, nullptr, nullptr, bn1_g, bn1_b, bn1_m, bn1_v);

    // 8. h2 = gelu(bn2(dwconv3x3(h1))) -> fp16   (2 channels/block)
    dw_k<<<BB * MRC / 2, 256>>>(dw, bn2_g, bn2_b, bn2_m, bn2_v);

    // 9. out = x1h + bn3(w2 @ h2)   (KC=64)
    mgemm_k<5,1,1,0,64><<<dim3(CC / 128, 8, BB), 256, 107520>>>(
        wh + WOFF_W2, nullptr, h2h, (float*)d_out, nullptr, CC, 1024, 0,
        nullptr, x1h, nullptr, bn3_g, bn3_b, bn3_m, bn3_v);
}

// round 17
// speedup vs baseline: 1.0453x; 1.0203x over previous
#include <cuda_runtime.h>
#include <cuda_fp16.h>
#include <cstdint>
#include <math.h>

// ---------------- problem constants ----------------
#define BB   16
#define CC   256
#define HWSZ 1024
#define DH   32
#define HEADS 8
#define KTOP 4
#define MRC  1024
#define NWIN 64
#define EPSV 1e-5f

// pre-split weight offsets (halves)
#define WOFF_QKV 0
#define WOFF_MRG 196608
#define WOFF_W1  262144
#define WOFF_W2  524288
#define WTOT     786432

// ---------------- device scratch ----------------
__device__ float  g_qm  [BB * HEADS * NWIN * DH];
__device__ float  g_km  [BB * HEADS * NWIN * DH];
__device__ int    g_idx [BB * HEADS * NWIN * KTOP];
__device__ __half g_h0h [BB * CC  * HWSZ];
__device__ __half g_qkvh[BB * 3*CC * HWSZ];
__device__ __half g_msgh[BB * CC  * HWSZ];
__device__ __half g_x1h [BB * CC  * HWSZ];
__device__ __half g_h1h [BB * MRC * HWSZ];
__device__ __half g_h2h [BB * MRC * HWSZ];
__device__ __half g_wh  [WTOT];
__device__ __half g_wl  [196608];   // lo only for qkv (q,k rows used)

__device__ __forceinline__ float gelu_f(float x) {
    return 0.5f * x * (1.0f + erff(x * 0.7071067811865475f));
}

// ---------------- fp16 warp MMA + ldmatrix + cp.async ----------------
__device__ __forceinline__ void mma_f16(float* d, const uint32_t* a, uint32_t b0, uint32_t b1) {
    asm volatile(
        "mma.sync.aligned.m16n8k16.row.col.f32.f16.f16.f32 "
        "{%0,%1,%2,%3}, {%4,%5,%6,%7}, {%8,%9}, {%0,%1,%2,%3};"
        : "+f"(d[0]), "+f"(d[1]), "+f"(d[2]), "+f"(d[3])
        : "r"(a[0]), "r"(a[1]), "r"(a[2]), "r"(a[3]), "r"(b0), "r"(b1));
}
__device__ __forceinline__ void ldsm_x2_t(uint32_t& r0, uint32_t& r1, uint32_t addr) {
    asm volatile("ldmatrix.sync.aligned.m8n8.x2.trans.shared.b16 {%0,%1}, [%2];"
                 : "=r"(r0), "=r"(r1) : "r"(addr));
}
__device__ __forceinline__ void ldsm_x4(uint32_t* r, uint32_t addr) {
    asm volatile("ldmatrix.sync.aligned.m8n8.x4.shared.b16 {%0,%1,%2,%3}, [%4];"
                 : "=r"(r[0]), "=r"(r[1]), "=r"(r[2]), "=r"(r[3]) : "r"(addr));
}
__device__ __forceinline__ void ldsm_x4_t(uint32_t* r, uint32_t addr) {
    asm volatile("ldmatrix.sync.aligned.m8n8.x4.trans.shared.b16 {%0,%1,%2,%3}, [%4];"
                 : "=r"(r[0]), "=r"(r[1]), "=r"(r[2]), "=r"(r[3]) : "r"(addr));
}
__device__ __forceinline__ uint32_t smem_u32(const void* p) {
    uint32_t a;
    asm("{ .reg .u64 t; cvta.to.shared.u64 t, %1; cvt.u32.u64 %0, t; }" : "=r"(a) : "l"(p));
    return a;
}
__device__ __forceinline__ void cp16(uint32_t dst, const void* src) {
    asm volatile("cp.async.cg.shared.global [%0], [%1], 16;" :: "r"(dst), "l"(src) : "memory");
}
#define CP_COMMIT() asm volatile("cp.async.commit_group;" ::: "memory")
#define CP_WAIT(N)  asm volatile("cp.async.wait_group %0;" :: "n"(N) : "memory")
__device__ __forceinline__ void cvt_split(float x, __half& h, __half& l) {
    h = __float2half_rn(x);
    l = __float2half_rn(x - __half2float(h));
}

#define A_STR 136

// ---------------- weight pre-split ----------------
__global__ void wsplit_k(const float* __restrict__ wqkv, const float* __restrict__ wmrg,
                         const float* __restrict__ w1,   const float* __restrict__ w2) {
    int i = blockIdx.x * 256 + threadIdx.x;
    if (i >= WTOT) return;
    if (i < WOFF_MRG) {
        __half h, l; cvt_split(wqkv[i], h, l);
        g_wh[i] = h; g_wl[i] = l;
    } else if (i < WOFF_W1) {
        g_wh[i] = __float2half_rn(wmrg[i - WOFF_MRG]);
    } else if (i < WOFF_W2) {
        g_wh[i] = __float2half_rn(w1[i - WOFF_W1]);
    } else {
        g_wh[i] = __float2half_rn(w2[i - WOFF_W2]);
    }
}

// ---------------- h0 = gelu(bn0(x)) -> fp16 ----------------
__global__ void bn0_gelu_k(const float* __restrict__ x,
                           const float* __restrict__ g, const float* __restrict__ b,
                           const float* __restrict__ m, const float* __restrict__ v) {
    int i = blockIdx.x * 256 + threadIdx.x;
    if (i >= BB * CC * HWSZ / 4) return;
    int c = (i >> 8) & (CC - 1);
    float s = g[c] * rsqrtf(v[c] + EPSV);
    float sh = b[c] - m[c] * s;
    float4 xv = ((const float4*)x)[i];
    __half2 h0 = __floats2half2_rn(gelu_f(xv.x * s + sh), gelu_f(xv.y * s + sh));
    __half2 h1 = __floats2half2_rn(gelu_f(xv.z * s + sh), gelu_f(xv.w * s + sh));
    uint2 u; u.x = *(uint32_t*)&h0; u.y = *(uint32_t*)&h1;
    ((uint2*)g_h0h)[i] = u;
}

// ---------------- tensor-core fused GEMM (cp.async 3-stage, ldmatrix, KC-chunk) ----------------
// PASSES: 1 = hiW*hiA; 2 = + loW*hiA (W exact, A rounded)
// MODE 0: plain; 1: Res32 + acc + bias; 2: gelu(bn(acc)); 5: ResH + bn(acc)
template<int MODE, int PASSES, int WF32, int WF16, int KC>
__global__ void __launch_bounds__(256, 2)
mgemm_k(const __half* __restrict__ Whg, const __half* __restrict__ Wlg,
        const __half* __restrict__ Ahg,
        float* __restrict__ Out, __half* __restrict__ Outh, int O, int Kd,
        const float* __restrict__ Res, const __half* __restrict__ ResH,
        const float* __restrict__ bias,
        const float* __restrict__ g,  const float* __restrict__ bb,
        const float* __restrict__ mm, const float* __restrict__ vv) {
    constexpr int W_STR = (KC == 64) ? 72 : 40;
    constexpr int WH_B  = 128 * W_STR * 2;
    constexpr int WL_O  = WH_B;
    constexpr int AH_O  = (PASSES >= 2) ? 2 * WH_B : WH_B;
    constexpr int STG   = AH_O + KC * A_STR * 2;
    constexpr int KSN   = KC / 16;
    constexpr int WCP   = KC / 16;
    constexpr int ACP   = KC / 16;
    constexpr int WROWDIV = KC / 8;

    extern __shared__ char smc[];
    const int tid = threadIdx.x, lane = tid & 31, warp = tid >> 5;
    const int b = blockIdx.z, om = blockIdx.x * 128, n0 = blockIdx.y * 128;
    const int wm = warp >> 1, wn = warp & 1;
    const int gq = lane >> 2, tq = lane & 3;
    const uint32_t smbase = smem_u32(smc);

    const __half* Abh = Ahg + (size_t)b * Kd * HWSZ + n0;

    float acc[2][8][4];
    #pragma unroll
    for (int mt = 0; mt < 2; mt++)
        #pragma unroll
        for (int nt = 0; nt < 8; nt++)
            #pragma unroll
            for (int r = 0; r < 4; r++) acc[mt][nt][r] = 0.f;

    const uint32_t aoff = (uint32_t)(((lane & 15) * A_STR + wn * 64) * 2);
    const uint32_t woff = (uint32_t)(((wm * 32 + (lane & 7) + ((lane >> 3) & 1) * 8) * W_STR
                                     + (lane >> 4) * 8) * 2);
    const int nch = Kd / KC;

    auto issue = [&](int ch, int st) {
        int k0 = ch * KC;
        uint32_t stu = smbase + (uint32_t)st * STG;
        #pragma unroll
        for (int it = 0; it < WCP; it++) {
            int e = tid + it * 256;
            int row = e / WROWDIV, cc = e % WROWDIV;
            cp16(stu + row * (W_STR * 2) + cc * 16,
                 Whg + (size_t)(om + row) * Kd + k0 + cc * 8);
            if (PASSES >= 2)
                cp16(stu + WL_O + row * (W_STR * 2) + cc * 16,
                     Wlg + (size_t)(om + row) * Kd + k0 + cc * 8);
        }
        #pragma unroll
        for (int it = 0; it < ACP; it++) {
            int e = tid + it * 256;
            int row = e >> 4, col8 = (e & 15) * 8;
            cp16(stu + AH_O + (row * A_STR + col8) * 2, Abh + (size_t)(k0 + row) * HWSZ + col8);
        }
        CP_COMMIT();
    };

    issue(0, 0);
    issue(1, 1);

    int st = 0;
    for (int ch = 0; ch < nch; ch++) {
        if (ch + 1 < nch) { CP_WAIT(1); } else { CP_WAIT(0); }
        __syncthreads();
        if (ch + 2 < nch) {
            int st2 = st + 2; if (st2 >= 3) st2 -= 3;
            issue(ch + 2, st2);
        }

        uint32_t stu = smbase + (uint32_t)st * STG;

        #pragma unroll
        for (int ks = 0; ks < KSN; ks++) {
            uint32_t afh[2][4], afl[2][4];
            #pragma unroll
            for (int mt = 0; mt < 2; mt++) {
                uint32_t wa = stu + woff + (uint32_t)(mt * 16 * W_STR * 2 + ks * 32);
                ldsm_x4(afh[mt], wa);
                if (PASSES >= 2) ldsm_x4(afl[mt], wa + WL_O);
            }
            uint32_t abase_h = stu + AH_O + aoff + (uint32_t)ks * (16 * A_STR * 2);
            #pragma unroll
            for (int nt = 0; nt < 8; nt++) {
                uint32_t bh0, bh1;
                ldsm_x2_t(bh0, bh1, abase_h + nt * 16);
                #pragma unroll
                for (int mt = 0; mt < 2; mt++) {
                    mma_f16(acc[mt][nt], afh[mt], bh0, bh1);
                    if (PASSES >= 2) mma_f16(acc[mt][nt], afl[mt], bh0, bh1);
                }
            }
        }
        st = (st + 1 == 3) ? 0 : st + 1;
    }
    __syncthreads();

    // ---- epilogue ----
    #pragma unroll
    for (int mt = 0; mt < 2; mt++) {
        int o0 = om + wm * 32 + mt * 16 + gq;
        int o1 = o0 + 8;
        float s0 = 0.f, bs0 = 0.f, s1 = 0.f, bs1 = 0.f, bi0 = 0.f, bi1 = 0.f;
        if (MODE == 2 || MODE == 5) {
            s0 = g[o0] * rsqrtf(vv[o0] + EPSV); bs0 = bb[o0] - mm[o0] * s0;
            s1 = g[o1] * rsqrtf(vv[o1] + EPSV); bs1 = bb[o1] - mm[o1] * s1;
        }
        if (MODE == 1) { bi0 = bias[o0]; bi1 = bias[o1]; }
        #pragma unroll
        for (int nt = 0; nt < 8; nt++) {
            int n = n0 + wn * 64 + nt * 8 + 2 * tq;
            size_t oi0 = ((size_t)b * O + o0) * HWSZ + n;
            size_t oi1 = ((size_t)b * O + o1) * HWSZ + n;
            float r0 = acc[mt][nt][0], r1 = acc[mt][nt][1];
            float r2 = acc[mt][nt][2], r3 = acc[mt][nt][3];
            if (MODE == 1) {
                float2 e0 = *(const float2*)&Res[oi0];
                float2 e1 = *(const float2*)&Res[oi1];
                r0 += e0.x + bi0; r1 += e0.y + bi0;
                r2 += e1.x + bi1; r3 += e1.y + bi1;
            }
            if (MODE == 2) {
                r0 = gelu_f(r0 * s0 + bs0); r1 = gelu_f(r1 * s0 + bs0);
                r2 = gelu_f(r2 * s1 + bs1); r3 = gelu_f(r3 * s1 + bs1);
            }
            if (MODE == 5) {
                __half2 e0 = *(const __half2*)&ResH[oi0];
                __half2 e1 = *(const __half2*)&ResH[oi1];
                r0 = __low2float(e0) + r0 * s0 + bs0;
                r1 = __high2float(e0) + r1 * s0 + bs0;
                r2 = __low2float(e1) + r2 * s1 + bs1;
                r3 = __high2float(e1) + r3 * s1 + bs1;
            }
            if (WF32) {
                float2 v0 = {r0, r1}, v1 = {r2, r3};
                *(float2*)&Out[oi0] = v0;
                *(float2*)&Out[oi1] = v1;
            }
            if (WF16) {
                __half2 hv0 = __floats2half2_rn(r0, r1);
                __half2 hv1 = __floats2half2_rn(r2, r3);
                *(__half2*)&Outh[oi0] = hv0;
                *(__half2*)&Outh[oi1] = hv1;
            }
        }
    }
}

// ---------------- window means: block per (b,h,dpair) ----------------
__global__ void wmean_k() {
    int bid = blockIdx.x;
    int dp = bid & 15, h = (bid >> 4) & 7, b = bid >> 7;
    int d0 = dp * 2;
    int tid = threadIdx.x;
    __shared__ float spq[2][256], spk[2][256];
    const __half* qpl = g_qkvh + ((size_t)b * 3 * CC + h * DH + d0) * HWSZ;
    const __half* kpl = qpl + (size_t)CC * HWSZ;
    #pragma unroll
    for (int i = 0; i < 2; i++) {
        uint2 uq = ((const uint2*)(qpl + (size_t)i * HWSZ))[tid];
        uint2 uk = ((const uint2*)(kpl + (size_t)i * HWSZ))[tid];
        __half2 qa = *(__half2*)&uq.x, qb = *(__half2*)&uq.y;
        __half2 ka = *(__half2*)&uk.x, kb = *(__half2*)&uk.y;
        spq[i][tid] = __low2float(qa) + __high2float(qa) + __low2float(qb) + __high2float(qb);
        spk[i][tid] = __low2float(ka) + __high2float(ka) + __low2float(kb) + __high2float(kb);
    }
    __syncthreads();
    if (tid < 128) {
        int i = tid >> 6, w = tid & 63;
        int wy = w >> 3, wx = w & 7;
        int base = wy * 32 + wx;
        float sq = spq[i][base] + spq[i][base + 8] + spq[i][base + 16] + spq[i][base + 24];
        float sk = spk[i][base] + spk[i][base + 8] + spk[i][base + 16] + spk[i][base + 24];
        size_t o = ((size_t)(b * 8 + h) * 64 + w) * DH + d0 + i;
        g_qm[o] = sq * 0.0625f;
        g_km[o] = sk * 0.0625f;
    }
}

// ---------------- affinity + exact top-4 (2-way split) ----------------
__global__ void topk_k() {
    int bh = blockIdx.x >> 1;
    int half = blockIdx.x & 1;
    __shared__ float kt[32][65];
    __shared__ float qs[64][32];
    int tid = threadIdx.x, warp = tid >> 5, lane = tid & 31;
    for (int e = tid; e < 2048; e += 256) {
        int j = e >> 5, d = e & 31;
        kt[d][j] = g_km[(size_t)bh * 2048 + e];
        qs[j][d] = g_qm[(size_t)bh * 2048 + e];
    }
    __syncthreads();
    for (int ii = 0; ii < 4; ii++) {
        int i = half * 32 + warp * 4 + ii;
        float s0 = 0.f, s1 = 0.f;
        #pragma unroll
        for (int d = 0; d < 32; d++) {
            float q = qs[i][d];
            s0 += q * kt[d][lane];
            s1 += q * kt[d][lane + 32];
        }
        float v0 = s0, v1 = s1;
        #pragma unroll
        for (int t = 0; t < KTOP; t++) {
            float bvv; int bj;
            if (v0 >= v1) { bvv = v0; bj = lane; } else { bvv = v1; bj = lane + 32; }
            #pragma unroll
            for (int off = 16; off; off >>= 1) {
                float ov = __shfl_xor_sync(0xffffffffu, bvv, off);
                int   oj = __shfl_xor_sync(0xffffffffu, bj,  off);
                if (ov > bvv || (ov == bvv && oj < bj)) { bvv = ov; bj = oj; }
            }
            if (lane == 0) g_idx[((size_t)bh * 64 + i) * KTOP + t] = bj;
            if (bj == lane)      v0 = -INFINITY;
            if (bj == lane + 32) v1 = -INFINITY;
        }
    }
}

// ---------------- gathered window attention (2 windows per block) ----------------
#define QT_STR 24
#define KV_STR 72
#define SS_STR 68
#define P_STR  72
__global__ void __launch_bounds__(256) attn_k() {
    int bid = blockIdx.x;                  // b*256 + h*32 + npair
    int npair = bid & 31;
    int h = (bid >> 5) & 7;
    int b = bid >> 8;
    __shared__ __half qh[2][32 * QT_STR];
    __shared__ __half kh[2][32 * KV_STR];
    __shared__ __half vh[2][32 * KV_STR];
    __shared__ float  ss[2][16 * SS_STR];
    __shared__ __half ph[2][16 * P_STR];
    __shared__ int    widx[2][KTOP];
    int tid = threadIdx.x;
    int sub = tid >> 7;                    // 0/1 window within pair
    int stid = tid & 127;
    int n = npair * 2 + sub;
    size_t widbase = ((size_t)(b * HEADS + h) * NWIN + n) * KTOP;
    if (stid < KTOP) widx[sub][stid] = g_idx[widbase + stid];
    __syncthreads();

    int wy = n >> 3, wx = n & 7;
    const __half* qbase = g_qkvh + ((size_t)b * 3 * CC + h * DH) * HWSZ;
    const __half* kbase = qbase + (size_t)CC * HWSZ;
    const __half* vbase = qbase + (size_t)2 * CC * HWSZ;

    {
        int d = stid >> 2, tj = stid & 3;
        int hw = ((wy * 4 + tj) << 5) + wx * 4;
        uint2 u = *(const uint2*)(qbase + (size_t)d * HWSZ + hw);
        *(uint2*)&qh[sub][d * QT_STR + tj * 4] = u;
    }
    for (int e = stid; e < 512; e += 128) {
        int d = e >> 4, kq = e & 15;
        int j = widx[sub][kq >> 2];
        int tj = kq & 3;
        int hw = (((j >> 3) * 4 + tj) << 5) + (j & 7) * 4;
        uint2 uk = *(const uint2*)(kbase + (size_t)d * HWSZ + hw);
        uint2 uv = *(const uint2*)(vbase + (size_t)d * HWSZ + hw);
        *(uint2*)&kh[sub][d * KV_STR + kq * 4] = uk;
        *(uint2*)&vh[sub][d * KV_STR + kq * 4] = uv;
    }
    __syncthreads();

    int swarp = (tid >> 5) & 3, lane = tid & 31;
    int gq = lane >> 2, tq = lane & 3;
    const float scale = 0.17677669529663687f;
    const uint32_t qsm = smem_u32(qh[sub]);
    const uint32_t ksm = smem_u32(kh[sub]);
    const uint32_t qloff = (uint32_t)((((lane & 7) + (lane >> 4) * 8) * QT_STR
                                      + ((lane >> 3) & 1) * 8) * 2);
    const uint32_t kloff = (uint32_t)(((lane & 15) * KV_STR + swarp * 16) * 2);

    {
        float sc0[4] = {0.f, 0.f, 0.f, 0.f};
        float sc1[4] = {0.f, 0.f, 0.f, 0.f};
        #pragma unroll
        for (int ks = 0; ks < 2; ks++) {
            uint32_t ah[4];
            ldsm_x4_t(ah, qsm + qloff + (uint32_t)(ks * 16 * QT_STR * 2));
            uint32_t kb0, kb1;
            ldsm_x2_t(kb0, kb1, ksm + kloff + (uint32_t)(ks * 16 * KV_STR * 2));
            mma_f16(sc0, ah, kb0, kb1);
            uint32_t kb2, kb3;
            ldsm_x2_t(kb2, kb3, ksm + kloff + (uint32_t)(ks * 16 * KV_STR * 2) + 16);
            mma_f16(sc1, ah, kb2, kb3);
        }
        #pragma unroll
        for (int nt = 0; nt < 2; nt++) {
            const float* sc = nt ? sc1 : sc0;
            int c0 = swarp * 16 + nt * 8 + 2 * tq;
            ss[sub][gq * SS_STR + c0]           = sc[0] * scale;
            ss[sub][gq * SS_STR + c0 + 1]       = sc[1] * scale;
            ss[sub][(gq + 8) * SS_STR + c0]     = sc[2] * scale;
            ss[sub][(gq + 8) * SS_STR + c0 + 1] = sc[3] * scale;
        }
    }
    __syncthreads();

    #pragma unroll
    for (int rr = 0; rr < 4; rr++) {
        int row = swarp * 4 + rr;
        float s0 = ss[sub][row * SS_STR + lane];
        float s1 = ss[sub][row * SS_STR + lane + 32];
        float mx = fmaxf(s0, s1);
        #pragma unroll
        for (int off = 16; off; off >>= 1) mx = fmaxf(mx, __shfl_xor_sync(0xffffffffu, mx, off));
        float e0 = expf(s0 - mx), e1 = expf(s1 - mx);
        float sum = e0 + e1;
        #pragma unroll
        for (int off = 16; off; off >>= 1) sum += __shfl_xor_sync(0xffffffffu, sum, off);
        float inv = 1.0f / sum;
        ph[sub][row * P_STR + lane]      = __float2half_rn(e0 * inv);
        ph[sub][row * P_STR + lane + 32] = __float2half_rn(e1 * inv);
    }
    __syncthreads();

    {
        float f[4] = {0.f, 0.f, 0.f, 0.f};
        #pragma unroll
        for (int ks = 0; ks < 4; ks++) {
            int cb = ks * 16 + 2 * tq;
            uint32_t ah[4];
            ah[0] = *(const uint32_t*)&ph[sub][gq * P_STR + cb];
            ah[1] = *(const uint32_t*)&ph[sub][(gq + 8) * P_STR + cb];
            ah[2] = *(const uint32_t*)&ph[sub][gq * P_STR + cb + 8];
            ah[3] = *(const uint32_t*)&ph[sub][(gq + 8) * P_STR + cb + 8];
            int d = swarp * 8 + gq;
            uint32_t bh0 = *(const uint32_t*)&vh[sub][d * KV_STR + cb];
            uint32_t bh1 = *(const uint32_t*)&vh[sub][d * KV_STR + cb + 8];
            mma_f16(f, ah, bh0, bh1);
        }
        __half* mbase = g_msgh + ((size_t)b * CC + h * DH) * HWSZ;
        int d0 = swarp * 8 + 2 * tq;
        int hwA = ((wy * 4 + (gq >> 2)) << 5) + wx * 4 + (gq & 3);
        int hwB = ((wy * 4 + ((gq + 8) >> 2)) << 5) + wx * 4 + ((gq + 8) & 3);
        mbase[(size_t)d0 * HWSZ + hwA]       = __float2half_rn(f[0]);
        mbase[(size_t)(d0 + 1) * HWSZ + hwA] = __float2half_rn(f[1]);
        mbase[(size_t)d0 * HWSZ + hwB]       = __float2half_rn(f[2]);
        mbase[(size_t)(d0 + 1) * HWSZ + hwB] = __float2half_rn(f[3]);
    }
}

// ---------------- depthwise 3x3 + bn2 + gelu (2 channels/block) ----------------
__global__ void dw_k(const float* __restrict__ dw,
                     const float* __restrict__ g2, const float* __restrict__ b2,
                     const float* __restrict__ m2, const float* __restrict__ v2) {
    int bc0 = blockIdx.x * 2;
    __shared__ float t[2][1024];
    __shared__ float wsh[2][9];
    int tid = threadIdx.x;
    #pragma unroll
    for (int i = 0; i < 2; i++) {
        const __half* p = g_h1h + (size_t)(bc0 + i) * HWSZ;
        uint2 u = ((const uint2*)p)[tid];
        __half2 a = *(__half2*)&u.x, bp = *(__half2*)&u.y;
        float4 f;
        f.x = __low2float(a);  f.y = __high2float(a);
        f.z = __low2float(bp); f.w = __high2float(bp);
        ((float4*)t[i])[tid] = f;
    }
    if (tid < 18) {
        int i = tid / 9, w = tid % 9;
        wsh[i][w] = dw[((bc0 + i) & (MRC - 1)) * 9 + w];
    }
    __syncthreads();
    int y = tid >> 3, x0 = (tid & 7) * 4;
    #pragma unroll
    for (int i = 0; i < 2; i++) {
        int c = (bc0 + i) & (MRC - 1);
        float s = g2[c] * rsqrtf(v2[c] + EPSV);
        float bs = b2[c] - m2[c] * s;
        __half* outp = g_h2h + (size_t)(bc0 + i) * HWSZ;
        float rp[4];
        #pragma unroll
        for (int j = 0; j < 4; j++) {
            int x = x0 + j;
            float acc = 0.f;
            #pragma unroll
            for (int dy = -1; dy <= 1; dy++) {
                int yy = y + dy;
                if (yy < 0 || yy > 31) continue;
                #pragma unroll
                for (int dx = -1; dx <= 1; dx++) {
                    int xx = x + dx;
                    if (xx < 0 || xx > 31) continue;
                    acc += wsh[i][(dy + 1) * 3 + (dx + 1)] * t[i][yy * 32 + xx];
                }
            }
            rp[j] = gelu_f(acc * s + bs);
        }
        __half2 o0 = __floats2half2_rn(rp[0], rp[1]);
        __half2 o1 = __floats2half2_rn(rp[2], rp[3]);
        uint2 u; u.x = *(uint32_t*)&o0; u.y = *(uint32_t*)&o1;
        ((uint2*)outp)[tid] = u;
    }
}

// ---------------- launcher ----------------
extern "C" void kernel_launch(void* const* d_in, const int* in_sizes, int n_in,
                              void* d_out, int out_size) {
    const float* x      = (const float*)d_in[0];
    const float* bn0_g  = (const float*)d_in[1];
    const float* bn0_b  = (const float*)d_in[2];
    const float* bn0_m  = (const float*)d_in[3];
    const float* bn0_v  = (const float*)d_in[4];
    const float* w_qkv  = (const float*)d_in[5];
    const float* w_mrg  = (const float*)d_in[6];
    const float* b_mrg  = (const float*)d_in[7];
    const float* w1     = (const float*)d_in[8];
    const float* bn1_g  = (const float*)d_in[9];
    const float* bn1_b  = (const float*)d_in[10];
    const float* bn1_m  = (const float*)d_in[11];
    const float* bn1_v  = (const float*)d_in[12];
    const float* dw     = (const float*)d_in[13];
    const float* bn2_g  = (const float*)d_in[14];
    const float* bn2_b  = (const float*)d_in[15];
    const float* bn2_m  = (const float*)d_in[16];
    const float* bn2_v  = (const float*)d_in[17];
    const float* w2     = (const float*)d_in[18];
    const float* bn3_g  = (const float*)d_in[19];
    const float* bn3_b  = (const float*)d_in[20];
    const float* bn3_m  = (const float*)d_in[21];
    const float* bn3_v  = (const float*)d_in[22];

    __half *wh, *wl, *h0h, *qkvh, *msgh, *x1h, *h1h, *h2h;
    cudaGetSymbolAddress((void**)&wh,   g_wh);
    cudaGetSymbolAddress((void**)&wl,   g_wl);
    cudaGetSymbolAddress((void**)&h0h,  g_h0h);
    cudaGetSymbolAddress((void**)&qkvh, g_qkvh);
    cudaGetSymbolAddress((void**)&msgh, g_msgh);
    cudaGetSymbolAddress((void**)&x1h,  g_x1h);
    cudaGetSymbolAddress((void**)&h1h,  g_h1h);
    cudaGetSymbolAddress((void**)&h2h,  g_h2h);

    cudaFuncSetAttribute((const void*)mgemm_k<0,2,0,1,32>, cudaFuncAttributeMaxDynamicSharedMemorySize, 87552);
    cudaFuncSetAttribute((const void*)mgemm_k<0,1,0,1,64>, cudaFuncAttributeMaxDynamicSharedMemorySize, 107520);
    cudaFuncSetAttribute((const void*)mgemm_k<1,1,0,1,64>, cudaFuncAttributeMaxDynamicSharedMemorySize, 107520);
    cudaFuncSetAttribute((const void*)mgemm_k<2,1,0,1,64>, cudaFuncAttributeMaxDynamicSharedMemorySize, 107520);
    cudaFuncSetAttribute((const void*)mgemm_k<5,1,1,0,64>, cudaFuncAttributeMaxDynamicSharedMemorySize, 107520);

    // 0. pre-split weights to fp16
    wsplit_k<<<(WTOT + 255) / 256, 256>>>(w_qkv, w_mrg, w1, w2);

    // 1. h0 = gelu(bn0(x)) -> fp16
    bn0_gelu_k<<<(BB * CC * HWSZ / 4 + 255) / 256, 256>>>(x, bn0_g, bn0_b, bn0_m, bn0_v);

    // 2a. q,k = w_qkv[0:512] @ h0   (2-pass, KC=32)
    mgemm_k<0,2,0,1,32><<<dim3(4, 8, BB), 256, 87552>>>(
        wh + WOFF_QKV, wl, h0h, nullptr, qkvh, 768, 256,
        nullptr, nullptr, nullptr, nullptr, nullptr, nullptr, nullptr);

    // 2b. v = w_qkv[512:768] @ h0   (1-pass, KC=64)
    mgemm_k<0,1,0,1,64><<<dim3(2, 8, BB), 256, 107520>>>(
        wh + WOFF_QKV + 512 * 256, nullptr, h0h, nullptr,
        qkvh + (size_t)512 * HWSZ, 768, 256,
        nullptr, nullptr, nullptr, nullptr, nullptr, nullptr, nullptr);

    // 3. window means (2 d per block)
    wmean_k<<<BB * HEADS * DH / 2, 256>>>();

    // 4. affinity + top-4 (2-way split)
    topk_k<<<BB * HEADS * 2, 256>>>();

    // 5. gathered attention (2 windows per block)
    attn_k<<<BB * HEADS * NWIN / 2, 256>>>();

    // 6. x1h = fp16(x + w_merge @ msg + b_merge)   (KC=64)
    mgemm_k<1,1,0,1,64><<<dim3(CC / 128, 8, BB), 256, 107520>>>(
        wh + WOFF_MRG, nullptr, msgh, nullptr, x1h, CC, 256,
        x, nullptr, b_mrg, nullptr, nullptr, nullptr, nullptr);

    // 7. h1 = gelu(bn1(w1 @ x1h)) -> fp16   (KC=64)
    mgemm_k<2,1,0,1,64><<<dim3(MRC / 128, 8, BB), 256, 107520>>>(
        wh + WOFF_W1, nullptr, x1h, nullptr, h1h, MRC, 256,
        nullptr, nullptr, nullptr, bn1_g, bn1_b, bn1_m, bn1_v);

    // 8. h2 = gelu(bn2(dwconv3x3(h1))) -> fp16   (2 channels/block)
    dw_k<<<BB * MRC / 2, 256>>>(dw, bn2_g, bn2_b, bn2_m, bn2_v);

    // 9. out = x1h + bn3(w2 @ h2)   (KC=64)
    mgemm_k<5,1,1,0,64><<<dim3(CC / 128, 8, BB), 256, 107520>>>(
        wh + WOFF_W2, nullptr, h2h, (float*)d_out, nullptr, CC, 1024,
        nullptr, x1h, nullptr, bn3_g, bn3_b, bn3_m, bn3_v);
}